// round 11
// baseline (speedup 1.0000x reference)
#include <cuda_runtime.h>
#include <math.h>
#include <stdint.h>

#define N_NODES 50000
#define N_EDGES 400000
#define EPB 64   // edges per block in k_edge

// Scale constants
#define INV_S64  0.125f                  // 1/sqrt(64)
#define INV_S32  0.17677669529663687f    // 1/sqrt(32)
#define INV_S10  0.31622776601683794f    // 1/sqrt(10)
#define INV_S96  0.10206207261596575f    // 1/sqrt(96)
#define INV_S3   0.57735026918962576f    // 1/sqrt(3)

// ---------------- scratch (device globals; no allocation allowed) ----------
__device__ __align__(16) float d_hs [N_NODES * 64];
__device__ __align__(16) float d_hv [N_NODES * 96];
__device__ __align__(16) float d_scs[N_NODES * 96];
__device__ __align__(16) float d_scv[N_NODES * 96];
__device__ __align__(16) float d_Ms [N_NODES * 96];
__device__ __align__(16) float d_Mv [N_NODES * 288];
__device__ float d_deg[N_NODES];
__device__ __align__(16) float d_gs [N_NODES * 64];
__device__ __align__(16) float d_v1 [N_NODES * 96];
__device__ float d_w2f[2][12288];       // Wfc2 tf32, MMA-fragment-packed, per layer

__device__ __forceinline__ float sigmoidf_(float x) { return 1.0f / (1.0f + __expf(-x)); }
__device__ __forceinline__ float siluf_(float x)    { return x / (1.0f + __expf(-x)); }

__device__ __forceinline__ float tf32r(float x) {
    uint32_t u;
    asm("cvt.rna.tf32.f32 %0, %1;" : "=r"(u) : "f"(x));
    return __uint_as_float(u);
}

__device__ __forceinline__ void mma_tf32(float c[4],
    uint32_t a0, uint32_t a1, uint32_t a2, uint32_t a3,
    uint32_t b0, uint32_t b1)
{
    asm volatile(
        "mma.sync.aligned.m16n8k8.row.col.f32.tf32.tf32.f32 "
        "{%0,%1,%2,%3},{%4,%5,%6,%7},{%8,%9},{%0,%1,%2,%3};"
        : "+f"(c[0]), "+f"(c[1]), "+f"(c[2]), "+f"(c[3])
        : "r"(a0), "r"(a1), "r"(a2), "r"(a3), "r"(b0), "r"(b1));
}

__device__ __forceinline__ void red4(float* p, float4 v) {
    atomicAdd(reinterpret_cast<float4*>(p), v);
}

// ---------------- degree + weight prep -------------------------------------
__global__ void k_deg_zero() {
    int i = blockIdx.x * blockDim.x + threadIdx.x;
    if (i < N_NODES) d_deg[i] = 0.0f;
}
__global__ void k_deg(const int* __restrict__ dst) {
    int i = blockIdx.x * blockDim.x + threadIdx.x;
    if (i < N_EDGES) atomicAdd(&d_deg[dst[i]], 1.0f);
}

// Pack Wfc2 (64k x 192n) into MMA B-fragment order, tf32-rounded.
__global__ void k_prep(const float* __restrict__ W2a, const float* __restrict__ W2b) {
    int t = blockIdx.x * 256 + threadIdx.x;
    if (t >= 24576) return;
    int lay = t / 12288, r = t % 12288;
    int S = r / 1536;
    int rem = r % 1536;
    int T = rem / 64;
    int rem2 = rem % 64;
    int half = rem2 >> 5, lane = rem2 & 31;
    int row = lane >> 2, kc = lane & 3;
    const float* W = lay ? W2b : W2a;
    d_w2f[lay][r] = tf32r(W[(8 * S + kc + 4 * half) * 192 + 8 * T + row]);
}

// ---------------- kernel A: node pre-linears (warp per 2 nodes) ------------
template <int OS, bool SCR>
__global__ void __launch_bounds__(256) k_node_pre(
    const float* __restrict__ ns_in, const float* __restrict__ nv_in,
    const float* __restrict__ attr,
    const float* __restrict__ Wscs, const float* __restrict__ Wscv,
    const float* __restrict__ W1s,  const float* __restrict__ W1v)
{
    const int l  = threadIdx.x & 31;
    const int n0 = (blockIdx.x * 8 + (threadIdx.x >> 5)) * 2;
    if (n0 >= N_NODES) return;
    const bool actB = (n0 + 1 < N_NODES);
    const int nA = n0, nB = actB ? n0 + 1 : n0;

    const float* ns = SCR ? d_gs : ns_in;
    const float* nv = SCR ? d_v1 : nv_in;

    float aA = attr[nA], aB = attr[nB];
    float nsA0 = ns[nA * 64 + l], nsA1 = ns[nA * 64 + 32 + l];
    float nsB0 = ns[nB * 64 + l], nsB1 = ns[nB * 64 + 32 + l];
    float nvA0 = nv[nA * 96 + l * 3 + 0], nvA1 = nv[nA * 96 + l * 3 + 1], nvA2 = nv[nA * 96 + l * 3 + 2];
    float nvB0 = nv[nB * 96 + l * 3 + 0], nvB1 = nv[nB * 96 + l * 3 + 1], nvB2 = nv[nB * 96 + l * 3 + 2];

    float hsA0 = 0.f, hsA1 = 0.f, scA0 = 0.f, scA1 = 0.f, scA2 = 0.f;
    float hsB0 = 0.f, hsB1 = 0.f, scB0 = 0.f, scB1 = 0.f, scB2 = 0.f;
#pragma unroll
    for (int u = 0; u < 64; ++u) {
        float w1a = W1s[u * 64 + l];
        float w1b = W1s[u * 64 + 32 + l];
        float wsa = Wscs[u * OS + l];
        float wsb = Wscs[u * OS + 32 + l];
        float wsc = (OS == 96) ? Wscs[u * OS + 64 + l] : 0.f;
        float nuA = __shfl_sync(0xffffffffu, (u < 32) ? nsA0 : nsA1, u & 31);
        float nuB = __shfl_sync(0xffffffffu, (u < 32) ? nsB0 : nsB1, u & 31);
        hsA0 += nuA * w1a; hsA1 += nuA * w1b;
        scA0 += nuA * wsa; scA1 += nuA * wsb;
        hsB0 += nuB * w1a; hsB1 += nuB * w1b;
        scB0 += nuB * wsa; scB1 += nuB * wsb;
        if (OS == 96) { scA2 += nuA * wsc; scB2 += nuB * wsc; }
    }

    float hvA0 = 0.f, hvA1 = 0.f, hvA2 = 0.f, svA0 = 0.f, svA1 = 0.f, svA2 = 0.f;
    float hvB0 = 0.f, hvB1 = 0.f, hvB2 = 0.f, svB0 = 0.f, svB1 = 0.f, svB2 = 0.f;
#pragma unroll
    for (int u = 0; u < 32; ++u) {
        float wl = W1v [u * 32 + l];
        float ws = Wscv[u * 32 + l];
        float bA0 = __shfl_sync(0xffffffffu, nvA0, u);
        float bA1 = __shfl_sync(0xffffffffu, nvA1, u);
        float bA2 = __shfl_sync(0xffffffffu, nvA2, u);
        float bB0 = __shfl_sync(0xffffffffu, nvB0, u);
        float bB1 = __shfl_sync(0xffffffffu, nvB1, u);
        float bB2 = __shfl_sync(0xffffffffu, nvB2, u);
        hvA0 += bA0 * wl; hvA1 += bA1 * wl; hvA2 += bA2 * wl;
        svA0 += bA0 * ws; svA1 += bA1 * ws; svA2 += bA2 * ws;
        hvB0 += bB0 * wl; hvB1 += bB1 * wl; hvB2 += bB2 * wl;
        svB0 += bB0 * ws; svB1 += bB1 * ws; svB2 += bB2 * ws;
    }

    {
        float fs = aA * INV_S64, fv = aA * INV_S32;
        d_hs[nA * 64 + l]       = hsA0 * fs;
        d_hs[nA * 64 + 32 + l]  = hsA1 * fs;
        d_scs[nA * OS + l]      = scA0 * fs;
        d_scs[nA * OS + 32 + l] = scA1 * fs;
        if (OS == 96) d_scs[nA * OS + 64 + l] = scA2 * fs;
        d_hv [nA * 96 + l * 3 + 0] = hvA0 * fv;
        d_hv [nA * 96 + l * 3 + 1] = hvA1 * fv;
        d_hv [nA * 96 + l * 3 + 2] = hvA2 * fv;
        d_scv[nA * 96 + l * 3 + 0] = svA0 * fv;
        d_scv[nA * 96 + l * 3 + 1] = svA1 * fv;
        d_scv[nA * 96 + l * 3 + 2] = svA2 * fv;
        d_Ms[nA * 96 + l] = 0.f; d_Ms[nA * 96 + 32 + l] = 0.f; d_Ms[nA * 96 + 64 + l] = 0.f;
#pragma unroll
        for (int r = 0; r < 9; ++r) d_Mv[nA * 288 + r * 32 + l] = 0.f;
    }
    if (actB) {
        float fs = aB * INV_S64, fv = aB * INV_S32;
        d_hs[nB * 64 + l]       = hsB0 * fs;
        d_hs[nB * 64 + 32 + l]  = hsB1 * fs;
        d_scs[nB * OS + l]      = scB0 * fs;
        d_scs[nB * OS + 32 + l] = scB1 * fs;
        if (OS == 96) d_scs[nB * OS + 64 + l] = scB2 * fs;
        d_hv [nB * 96 + l * 3 + 0] = hvB0 * fv;
        d_hv [nB * 96 + l * 3 + 1] = hvB1 * fv;
        d_hv [nB * 96 + l * 3 + 2] = hvB2 * fv;
        d_scv[nB * 96 + l * 3 + 0] = svB0 * fv;
        d_scv[nB * 96 + l * 3 + 1] = svB1 * fv;
        d_scv[nB * 96 + l * 3 + 2] = svB2 * fv;
        d_Ms[nB * 96 + l] = 0.f; d_Ms[nB * 96 + 32 + l] = 0.f; d_Ms[nB * 96 + 64 + l] = 0.f;
#pragma unroll
        for (int r = 0; r < 9; ++r) d_Mv[nB * 288 + r * 32 + l] = 0.f;
    }
}

// ---------------- kernel B: fused edge MLP (tf32 MMA) + messages + scatter -
// 64 edges / block, 256 threads (8 warps).
// smem UNION: phase-1/2 buffers {Wfc1 640 | esc 640 | hT 64*72} alias the
// phase-3 buffer s_w (64*196). Union size = 64*196 = 12544 floats = 50176 B.
// s_w is written only AFTER a barrier past the last s_hT read -> legal.
#define SH_STRIDE 72
#define SW_STRIDE 196
#define B_SMEM_FLOATS (64 * SW_STRIDE)        // 12544
#define B_SMEM_BYTES  (B_SMEM_FLOATS * 4)     // 50176

__global__ void __launch_bounds__(256, 4) k_edge(
    const float* __restrict__ esc, const float* __restrict__ sh,
    const int* __restrict__ src,   const int* __restrict__ dst,
    const float* __restrict__ Wfc1, int layer)
{
    extern __shared__ float sm[];
    float* s_w1  = sm;                  // 640   (dead after phase 1)
    float* s_esc = sm + 640;            // 640   (dead after phase 1)
    float* s_hT  = sm + 1280;           // 4608  (dead after phase-2 MMA loop)
    float* s_w   = sm;                  // 12544 (aliases all of the above)

    const int t  = threadIdx.x;
    const int e0 = blockIdx.x * EPB;
    const int lane = t & 31, wp = t >> 5;

    for (int i = t; i < 640; i += 256) s_w1[i]  = Wfc1[i];
    for (int i = t; i < 640; i += 256) s_esc[i] = esc[e0 * 10 + i];
    __syncthreads();

    // ---- phase 1: h = silu(esc @ Wfc1 / sqrt(10)), tf32-rounded, transposed ----
    {
        int e = t & 63, q = t >> 6;
        float es[10];
#pragma unroll
        for (int u = 0; u < 10; ++u) es[u] = s_esc[e * 10 + u];
#pragma unroll
        for (int c = 0; c < 16; ++c) {
            int col = q * 16 + c;
            float acc = 0.f;
#pragma unroll
            for (int u = 0; u < 10; ++u) acc += es[u] * s_w1[u * 64 + col];
            s_hT[col * SH_STRIDE + e] = tf32r(siluf_(acc * INV_S10));
        }
    }
    __syncthreads();

    // ---- phase 2: w = h @ Wfc2 / 8 via tf32 m16n8k8 MMA ----
    {
        const int m0   = (wp & 3) * 16;
        const int tb   = (wp >> 2) * 12;
        const int row  = lane >> 2, kc = lane & 3;
        const float* w2f = (const float*)d_w2f[layer];

        float c[12][4];
#pragma unroll
        for (int i = 0; i < 12; ++i)
#pragma unroll
            for (int j = 0; j < 4; ++j) c[i][j] = 0.f;

#pragma unroll
        for (int S = 0; S < 8; ++S) {
            int kk = S * 8;
            uint32_t a0 = __float_as_uint(s_hT[(kk + kc)     * SH_STRIDE + m0 + row]);
            uint32_t a1 = __float_as_uint(s_hT[(kk + kc)     * SH_STRIDE + m0 + row + 8]);
            uint32_t a2 = __float_as_uint(s_hT[(kk + kc + 4) * SH_STRIDE + m0 + row]);
            uint32_t a3 = __float_as_uint(s_hT[(kk + kc + 4) * SH_STRIDE + m0 + row + 8]);
#pragma unroll
            for (int tt = 0; tt < 12; ++tt) {
                int T = tb + tt;
                const float* bp = w2f + ((S * 24 + T) * 2) * 32 + lane;
                uint32_t b0 = __float_as_uint(__ldg(bp));
                uint32_t b1 = __float_as_uint(__ldg(bp + 32));
                mma_tf32(c[tt], a0, a1, a2, a3, b0, b1);
            }
        }
        // all warps done reading s_hT -> safe to overwrite the union with s_w
        __syncthreads();
#pragma unroll
        for (int tt = 0; tt < 12; ++tt) {
            int col = (tb + tt) * 8 + kc * 2;
            int r0  = m0 + row;
            s_w[r0 * SW_STRIDE + col]           = c[tt][0] * INV_S64;
            s_w[r0 * SW_STRIDE + col + 1]       = c[tt][1] * INV_S64;
            s_w[(r0 + 8) * SW_STRIDE + col]     = c[tt][2] * INV_S64;
            s_w[(r0 + 8) * SW_STRIDE + col + 1] = c[tt][3] * INV_S64;
        }
    }
    __syncthreads();

    // ---- phase 3: warp-per-edge messages, vectorized red.v4 scatter ----
    {
#pragma unroll
        for (int ei = 0; ei < 8; ++ei) {
            int e  = wp * 8 + ei;
            int ge = e0 + e;
            int sn = __ldg(src + ge), dn = __ldg(dst + ge);
            float4 sh4 = __ldg((const float4*)(sh + ge * 4));
            float s0 = sh4.x, vx = sh4.y, vy = sh4.z, vz = sh4.w;
            const float* we  = s_w + e * SW_STRIDE;
            const float* hsp = d_hs + sn * 64;
            const float* hvp = d_hv + sn * 96;
            float* msd = d_Ms + dn * 96;
            float* mvd = d_Mv + dn * 288;

            if (lane < 16) {
                int j0 = lane * 4;
                float4 h4 = *(const float4*)(hsp + j0);
                float4 wa = *(const float4*)(we + j0);
                red4(msd + j0, make_float4(h4.x * s0 * wa.x, h4.y * s0 * wa.y,
                                           h4.z * s0 * wa.z, h4.w * s0 * wa.w));
            } else if (lane < 24) {
                int jp0 = (lane - 16) * 4;
                const float* gp = hvp + jp0 * 3;
                float4 ga = *(const float4*)gp;
                float4 gb = *(const float4*)(gp + 4);
                float4 gc = *(const float4*)(gp + 8);
                float4 w4 = *(const float4*)(we + 160 + jp0);
                float4 v;
                v.x = (ga.x * vx + ga.y * vy + ga.z * vz) * INV_S3 * w4.x;
                v.y = (ga.w * vx + gb.x * vy + gb.y * vz) * INV_S3 * w4.y;
                v.z = (gb.z * vx + gb.w * vy + gc.x * vz) * INV_S3 * w4.z;
                v.w = (gc.y * vx + gc.z * vy + gc.w * vz) * INV_S3 * w4.w;
                red4(msd + 64 + jp0, v);
            }
            {
                int f0 = lane * 4;
                float v[4];
#pragma unroll
                for (int c2 = 0; c2 < 4; ++c2) {
                    int f = f0 + c2, j = f / 3, i2 = f - 3 * j;
                    float shvi = (i2 == 0) ? vx : ((i2 == 1) ? vy : vz);
                    v[c2] = hsp[j] * shvi * we[64 + j];
                }
                red4(mvd + f0, make_float4(v[0], v[1], v[2], v[3]));
                if (lane < 16) {
                    int f1 = 128 + lane * 4;
                    float u2[4];
#pragma unroll
                    for (int c2 = 0; c2 < 4; ++c2) {
                        int f = f1 + c2, j = f / 3, i2 = f - 3 * j;
                        float shvi = (i2 == 0) ? vx : ((i2 == 1) ? vy : vz);
                        u2[c2] = hsp[j] * shvi * we[64 + j];
                    }
                    red4(mvd + f1, make_float4(u2[0], u2[1], u2[2], u2[3]));
                }
            }
            if (lane < 24) {
                int i0 = lane * 4;
                float4 g4 = *(const float4*)(hvp + i0);
                float4 v;
                v.x = g4.x * s0 * we[128 + (i0    ) / 3];
                v.y = g4.y * s0 * we[128 + (i0 + 1) / 3];
                v.z = g4.z * s0 * we[128 + (i0 + 2) / 3];
                v.w = g4.w * s0 * we[128 + (i0 + 3) / 3];
                red4(mvd + 192 + i0, v);
            }
        }
    }
}

// ---------------- kernel C: node finalize (warp per 2 nodes) ---------------
template <int OS, bool L1>
__global__ void __launch_bounds__(256) k_node_post(
    const float* __restrict__ attr,
    const float* __restrict__ W2s, const float* __restrict__ W2v,
    const float* __restrict__ Wa,  float* __restrict__ out)
{
    const int l  = threadIdx.x & 31;
    const int n0 = (blockIdx.x * 8 + (threadIdx.x >> 5)) * 2;
    if (n0 >= N_NODES) return;
    const bool actB = (n0 + 1 < N_NODES);
    const int nA = n0, nB = actB ? n0 + 1 : n0;

    float aA = attr[nA], aB = attr[nB];
    float idA = 1.0f / fmaxf(d_deg[nA], 1.0f);
    float idB = 1.0f / fmaxf(d_deg[nB], 1.0f);

    float msA[3], msB[3], mvA[3][3], mvB[3][3];
#pragma unroll
    for (int r = 0; r < 3; ++r) {
        msA[r] = d_Ms[nA * 96 + r * 32 + l] * idA;
        msB[r] = d_Ms[nB * 96 + r * 32 + l] * idB;
#pragma unroll
        for (int i = 0; i < 3; ++i) {
            mvA[r][i] = d_Mv[nA * 288 + (r * 32 + l) * 3 + i] * idA;
            mvB[r][i] = d_Mv[nB * 288 + (r * 32 + l) * 3 + i] * idB;
        }
    }

    float wa0 = Wa[l], wa1 = Wa[32 + l], wa2 = Wa[64 + l];
    float apA = msA[0] * wa0 + msA[1] * wa1 + msA[2] * wa2;
    float apB = msB[0] * wa0 + msB[1] * wa1 + msB[2] * wa2;
#pragma unroll
    for (int o = 16; o > 0; o >>= 1) {
        apA += __shfl_xor_sync(0xffffffffu, apA, o);
        apB += __shfl_xor_sync(0xffffffffu, apB, o);
    }
    float alA = apA * INV_S96 * aA;
    float alB = apB * INV_S96 * aB;

    float osA0 = 0.f, osA1 = 0.f, osA2 = 0.f, ovA0 = 0.f, ovA1 = 0.f, ovA2 = 0.f;
    float osB0 = 0.f, osB1 = 0.f, osB2 = 0.f, ovB0 = 0.f, ovB1 = 0.f, ovB2 = 0.f;
#pragma unroll
    for (int u = 0; u < 96; ++u) {
        int r = u >> 5, lu = u & 31;
        float w0 = W2s[u * OS + l];
        float w1 = W2s[u * OS + 32 + l];
        float w2 = (OS == 96) ? W2s[u * OS + 64 + l] : 0.f;
        float wv = W2v[u * 32 + l];
        float mA  = __shfl_sync(0xffffffffu, msA[r], lu);
        float mB  = __shfl_sync(0xffffffffu, msB[r], lu);
        float vA0 = __shfl_sync(0xffffffffu, mvA[r][0], lu);
        float vA1 = __shfl_sync(0xffffffffu, mvA[r][1], lu);
        float vA2 = __shfl_sync(0xffffffffu, mvA[r][2], lu);
        float vB0 = __shfl_sync(0xffffffffu, mvB[r][0], lu);
        float vB1 = __shfl_sync(0xffffffffu, mvB[r][1], lu);
        float vB2 = __shfl_sync(0xffffffffu, mvB[r][2], lu);
        osA0 += mA * w0; osA1 += mA * w1;
        osB0 += mB * w0; osB1 += mB * w1;
        if (OS == 96) { osA2 += mA * w2; osB2 += mB * w2; }
        ovA0 += vA0 * wv; ovA1 += vA1 * wv; ovA2 += vA2 * wv;
        ovB0 += vB0 * wv; ovB1 += vB1 * wv; ovB2 += vB2 * wv;
    }

    {
        float f = aA * INV_S96;
        float sA = d_scs[nA * OS + l]      + alA * (osA0 * f);
        float sB = d_scs[nA * OS + 32 + l] + alA * (osA1 * f);
        float sC = (OS == 96) ? (d_scs[nA * OS + 64 + l] + alA * (osA2 * f)) : 0.f;
        float v0 = d_scv[nA * 96 + l * 3 + 0] + alA * (ovA0 * f);
        float v1 = d_scv[nA * 96 + l * 3 + 1] + alA * (ovA1 * f);
        float v2 = d_scv[nA * 96 + l * 3 + 2] + alA * (ovA2 * f);
        if (L1) {
            d_gs[nA * 64 + l]      = siluf_(sA);
            d_gs[nA * 64 + 32 + l] = siluf_(sB);
            float sg = sigmoidf_(sC);
            d_v1[nA * 96 + l * 3 + 0] = v0 * sg;
            d_v1[nA * 96 + l * 3 + 1] = v1 * sg;
            d_v1[nA * 96 + l * 3 + 2] = v2 * sg;
        } else {
            out[nA * 160 + l]      = sA;
            out[nA * 160 + 32 + l] = sB;
            out[nA * 160 + 64 + l * 3 + 0] = v0;
            out[nA * 160 + 64 + l * 3 + 1] = v1;
            out[nA * 160 + 64 + l * 3 + 2] = v2;
        }
    }
    if (actB) {
        float f = aB * INV_S96;
        float sA = d_scs[nB * OS + l]      + alB * (osB0 * f);
        float sB2 = d_scs[nB * OS + 32 + l] + alB * (osB1 * f);
        float sC = (OS == 96) ? (d_scs[nB * OS + 64 + l] + alB * (osB2 * f)) : 0.f;
        float v0 = d_scv[nB * 96 + l * 3 + 0] + alB * (ovB0 * f);
        float v1 = d_scv[nB * 96 + l * 3 + 1] + alB * (ovB1 * f);
        float v2 = d_scv[nB * 96 + l * 3 + 2] + alB * (ovB2 * f);
        if (L1) {
            d_gs[nB * 64 + l]      = siluf_(sA);
            d_gs[nB * 64 + 32 + l] = siluf_(sB2);
            float sg = sigmoidf_(sC);
            d_v1[nB * 96 + l * 3 + 0] = v0 * sg;
            d_v1[nB * 96 + l * 3 + 1] = v1 * sg;
            d_v1[nB * 96 + l * 3 + 2] = v2 * sg;
        } else {
            out[nB * 160 + l]      = sA;
            out[nB * 160 + 32 + l] = sB2;
            out[nB * 160 + 64 + l * 3 + 0] = v0;
            out[nB * 160 + 64 + l * 3 + 1] = v1;
            out[nB * 160 + 64 + l * 3 + 2] = v2;
        }
    }
}

// ---------------- launch ----------------------------------------------------
extern "C" void kernel_launch(void* const* d_in, const int* in_sizes, int n_in,
                              void* d_out, int out_size)
{
    const float* node_s = (const float*)d_in[0];
    const float* node_v = (const float*)d_in[1];
    const float* attr   = (const float*)d_in[2];
    const int*   src    = (const int*)d_in[3];
    const int*   dst    = (const int*)d_in[4];
    const float* sh     = (const float*)d_in[5];
    const float* esc    = (const float*)d_in[6];
    const float* w1[9];
    const float* w2[9];
    for (int i = 0; i < 9; ++i) { w1[i] = (const float*)d_in[7 + i]; w2[i] = (const float*)d_in[16 + i]; }
    float* out = (float*)d_out;

    cudaFuncSetAttribute(k_edge, cudaFuncAttributeMaxDynamicSharedMemorySize, B_SMEM_BYTES);

    const int NPB = 16;  // nodes per block (8 warps x 2)
    const int nodeBlocks = (N_NODES + NPB - 1) / NPB;

    k_deg_zero<<<(N_NODES + 255) / 256, 256>>>();
    k_deg<<<(N_EDGES + 255) / 256, 256>>>(dst);
    k_prep<<<96, 256>>>(w1[5], w2[5]);

    // ---- layer 1 (o_s = 96) ----
    k_node_pre<96, false><<<nodeBlocks, 256>>>(node_s, node_v, attr,
                                               w1[0], w1[1], w1[2], w1[3]);
    k_edge<<<N_EDGES / EPB, 256, B_SMEM_BYTES>>>(esc, sh, src, dst, w1[4], 0);
    k_node_post<96, true><<<nodeBlocks, 256>>>(attr, w1[6], w1[7], w1[8], out);

    // ---- layer 2 (o_s = 64) ----
    k_node_pre<64, true><<<nodeBlocks, 256>>>(nullptr, nullptr, attr,
                                              w2[0], w2[1], w2[2], w2[3]);
    k_edge<<<N_EDGES / EPB, 256, B_SMEM_BYTES>>>(esc, sh, src, dst, w2[4], 1);
    k_node_post<64, false><<<nodeBlocks, 256>>>(attr, w2[6], w2[7], w2[8], out);

    (void)in_sizes; (void)n_in; (void)out_size;
}

// round 13
// speedup vs baseline: 1.3667x; 1.3667x over previous
#include <cuda_runtime.h>
#include <math.h>
#include <stdint.h>

#define N_NODES 50000
#define N_EDGES 400000
#define EPB 32   // edges per block in k_edge

// Scale constants
#define INV_S64  0.125f                  // 1/sqrt(64)
#define INV_S32  0.17677669529663687f    // 1/sqrt(32)
#define INV_S10  0.31622776601683794f    // 1/sqrt(10)
#define INV_S96  0.10206207261596575f    // 1/sqrt(96)
#define INV_S3   0.57735026918962576f    // 1/sqrt(3)

// ---------------- scratch (device globals; no allocation allowed) ----------
__device__ __align__(16) float d_hs [N_NODES * 64];
__device__ __align__(16) float d_hv [N_NODES * 96];
__device__ __align__(16) float d_scs[N_NODES * 96];
__device__ __align__(16) float d_scv[N_NODES * 96];
__device__ __align__(16) float d_Ms [N_NODES * 96];
__device__ __align__(16) float d_Mv [N_NODES * 288];
__device__ float d_deg[N_NODES];
__device__ __align__(16) float d_gs [N_NODES * 64];
__device__ __align__(16) float d_v1 [N_NODES * 96];
__device__ float d_w2f[2][12288];       // Wfc2 tf32, MMA-fragment-packed, per layer

__device__ __forceinline__ float sigmoidf_(float x) { return 1.0f / (1.0f + __expf(-x)); }
__device__ __forceinline__ float siluf_(float x)    { return x / (1.0f + __expf(-x)); }

__device__ __forceinline__ float tf32r(float x) {
    uint32_t u;
    asm("cvt.rna.tf32.f32 %0, %1;" : "=r"(u) : "f"(x));
    return __uint_as_float(u);
}

__device__ __forceinline__ void mma_tf32(float c[4],
    uint32_t a0, uint32_t a1, uint32_t a2, uint32_t a3,
    uint32_t b0, uint32_t b1)
{
    asm volatile(
        "mma.sync.aligned.m16n8k8.row.col.f32.tf32.tf32.f32 "
        "{%0,%1,%2,%3},{%4,%5,%6,%7},{%8,%9},{%0,%1,%2,%3};"
        : "+f"(c[0]), "+f"(c[1]), "+f"(c[2]), "+f"(c[3])
        : "r"(a0), "r"(a1), "r"(a2), "r"(a3), "r"(b0), "r"(b1));
}

__device__ __forceinline__ void red4(float* p, float4 v) {
    atomicAdd(reinterpret_cast<float4*>(p), v);
}

// ---------------- degree + weight prep -------------------------------------
__global__ void k_deg_zero() {
    int i = blockIdx.x * blockDim.x + threadIdx.x;
    if (i < N_NODES) d_deg[i] = 0.0f;
}
__global__ void k_deg(const int* __restrict__ dst) {
    int i = blockIdx.x * blockDim.x + threadIdx.x;
    if (i < N_EDGES) atomicAdd(&d_deg[dst[i]], 1.0f);
}

// Pack Wfc2 (64k x 192n) into MMA B-fragment order, tf32-rounded.
__global__ void k_prep(const float* __restrict__ W2a, const float* __restrict__ W2b) {
    int t = blockIdx.x * 256 + threadIdx.x;
    if (t >= 24576) return;
    int lay = t / 12288, r = t % 12288;
    int S = r / 1536;
    int rem = r % 1536;
    int T = rem / 64;
    int rem2 = rem % 64;
    int half = rem2 >> 5, lane = rem2 & 31;
    int row = lane >> 2, kc = lane & 3;
    const float* W = lay ? W2b : W2a;
    d_w2f[lay][r] = tf32r(W[(8 * S + kc + 4 * half) * 192 + 8 * T + row]);
}

// ---------------- kernel A: node pre-linears (warp per 2 nodes) ------------
template <int OS, bool SCR>
__global__ void __launch_bounds__(256) k_node_pre(
    const float* __restrict__ ns_in, const float* __restrict__ nv_in,
    const float* __restrict__ attr,
    const float* __restrict__ Wscs, const float* __restrict__ Wscv,
    const float* __restrict__ W1s,  const float* __restrict__ W1v)
{
    const int l  = threadIdx.x & 31;
    const int n0 = (blockIdx.x * 8 + (threadIdx.x >> 5)) * 2;
    if (n0 >= N_NODES) return;
    const bool actB = (n0 + 1 < N_NODES);
    const int nA = n0, nB = actB ? n0 + 1 : n0;

    const float* ns = SCR ? d_gs : ns_in;
    const float* nv = SCR ? d_v1 : nv_in;

    float aA = attr[nA], aB = attr[nB];
    float nsA0 = ns[nA * 64 + l], nsA1 = ns[nA * 64 + 32 + l];
    float nsB0 = ns[nB * 64 + l], nsB1 = ns[nB * 64 + 32 + l];
    float nvA0 = nv[nA * 96 + l * 3 + 0], nvA1 = nv[nA * 96 + l * 3 + 1], nvA2 = nv[nA * 96 + l * 3 + 2];
    float nvB0 = nv[nB * 96 + l * 3 + 0], nvB1 = nv[nB * 96 + l * 3 + 1], nvB2 = nv[nB * 96 + l * 3 + 2];

    float hsA0 = 0.f, hsA1 = 0.f, scA0 = 0.f, scA1 = 0.f, scA2 = 0.f;
    float hsB0 = 0.f, hsB1 = 0.f, scB0 = 0.f, scB1 = 0.f, scB2 = 0.f;
#pragma unroll
    for (int u = 0; u < 64; ++u) {
        float w1a = W1s[u * 64 + l];
        float w1b = W1s[u * 64 + 32 + l];
        float wsa = Wscs[u * OS + l];
        float wsb = Wscs[u * OS + 32 + l];
        float wsc = (OS == 96) ? Wscs[u * OS + 64 + l] : 0.f;
        float nuA = __shfl_sync(0xffffffffu, (u < 32) ? nsA0 : nsA1, u & 31);
        float nuB = __shfl_sync(0xffffffffu, (u < 32) ? nsB0 : nsB1, u & 31);
        hsA0 += nuA * w1a; hsA1 += nuA * w1b;
        scA0 += nuA * wsa; scA1 += nuA * wsb;
        hsB0 += nuB * w1a; hsB1 += nuB * w1b;
        scB0 += nuB * wsa; scB1 += nuB * wsb;
        if (OS == 96) { scA2 += nuA * wsc; scB2 += nuB * wsc; }
    }

    float hvA0 = 0.f, hvA1 = 0.f, hvA2 = 0.f, svA0 = 0.f, svA1 = 0.f, svA2 = 0.f;
    float hvB0 = 0.f, hvB1 = 0.f, hvB2 = 0.f, svB0 = 0.f, svB1 = 0.f, svB2 = 0.f;
#pragma unroll
    for (int u = 0; u < 32; ++u) {
        float wl = W1v [u * 32 + l];
        float ws = Wscv[u * 32 + l];
        float bA0 = __shfl_sync(0xffffffffu, nvA0, u);
        float bA1 = __shfl_sync(0xffffffffu, nvA1, u);
        float bA2 = __shfl_sync(0xffffffffu, nvA2, u);
        float bB0 = __shfl_sync(0xffffffffu, nvB0, u);
        float bB1 = __shfl_sync(0xffffffffu, nvB1, u);
        float bB2 = __shfl_sync(0xffffffffu, nvB2, u);
        hvA0 += bA0 * wl; hvA1 += bA1 * wl; hvA2 += bA2 * wl;
        svA0 += bA0 * ws; svA1 += bA1 * ws; svA2 += bA2 * ws;
        hvB0 += bB0 * wl; hvB1 += bB1 * wl; hvB2 += bB2 * wl;
        svB0 += bB0 * ws; svB1 += bB1 * ws; svB2 += bB2 * ws;
    }

    {
        float fs = aA * INV_S64, fv = aA * INV_S32;
        d_hs[nA * 64 + l]       = hsA0 * fs;
        d_hs[nA * 64 + 32 + l]  = hsA1 * fs;
        d_scs[nA * OS + l]      = scA0 * fs;
        d_scs[nA * OS + 32 + l] = scA1 * fs;
        if (OS == 96) d_scs[nA * OS + 64 + l] = scA2 * fs;
        d_hv [nA * 96 + l * 3 + 0] = hvA0 * fv;
        d_hv [nA * 96 + l * 3 + 1] = hvA1 * fv;
        d_hv [nA * 96 + l * 3 + 2] = hvA2 * fv;
        d_scv[nA * 96 + l * 3 + 0] = svA0 * fv;
        d_scv[nA * 96 + l * 3 + 1] = svA1 * fv;
        d_scv[nA * 96 + l * 3 + 2] = svA2 * fv;
        d_Ms[nA * 96 + l] = 0.f; d_Ms[nA * 96 + 32 + l] = 0.f; d_Ms[nA * 96 + 64 + l] = 0.f;
#pragma unroll
        for (int r = 0; r < 9; ++r) d_Mv[nA * 288 + r * 32 + l] = 0.f;
    }
    if (actB) {
        float fs = aB * INV_S64, fv = aB * INV_S32;
        d_hs[nB * 64 + l]       = hsB0 * fs;
        d_hs[nB * 64 + 32 + l]  = hsB1 * fs;
        d_scs[nB * OS + l]      = scB0 * fs;
        d_scs[nB * OS + 32 + l] = scB1 * fs;
        if (OS == 96) d_scs[nB * OS + 64 + l] = scB2 * fs;
        d_hv [nB * 96 + l * 3 + 0] = hvB0 * fv;
        d_hv [nB * 96 + l * 3 + 1] = hvB1 * fv;
        d_hv [nB * 96 + l * 3 + 2] = hvB2 * fv;
        d_scv[nB * 96 + l * 3 + 0] = svB0 * fv;
        d_scv[nB * 96 + l * 3 + 1] = svB1 * fv;
        d_scv[nB * 96 + l * 3 + 2] = svB2 * fv;
        d_Ms[nB * 96 + l] = 0.f; d_Ms[nB * 96 + 32 + l] = 0.f; d_Ms[nB * 96 + 64 + l] = 0.f;
#pragma unroll
        for (int r = 0; r < 9; ++r) d_Mv[nB * 288 + r * 32 + l] = 0.f;
    }
}

// ---------------- kernel B: fused edge MLP (tf32 MMA) + messages + scatter -
// 32 edges / block, 256 threads (8 warps), 4 CTAs/SM.
// Per-warp tile: 16m x 48n -> 6 n-tiles, 24 accumulator regs (fits 64-reg cap).
// smem UNION: {Wfc1 640 | esc 320 | hT 64*40} (3520) aliased by s_w 32*196 (6272).
#define SH_STRIDE 40
#define SW_STRIDE 196
#define B_SMEM_FLOATS (EPB * SW_STRIDE)       // 6272
#define B_SMEM_BYTES  (B_SMEM_FLOATS * 4)     // 25088

__global__ void __launch_bounds__(256, 4) k_edge(
    const float* __restrict__ esc, const float* __restrict__ sh,
    const int* __restrict__ src,   const int* __restrict__ dst,
    const float* __restrict__ Wfc1, int layer)
{
    extern __shared__ float sm[];
    float* s_w1  = sm;                  // 640  (dead after phase 1)
    float* s_esc = sm + 640;            // 320  (dead after phase 1)
    float* s_hT  = sm + 960;            // 2560 (dead after phase-2 MMA loop)
    float* s_w   = sm;                  // 6272 (aliases all of the above)

    const int t  = threadIdx.x;
    const int e0 = blockIdx.x * EPB;
    const int lane = t & 31, wp = t >> 5;

    for (int i = t; i < 640; i += 256) s_w1[i]  = Wfc1[i];
    for (int i = t; i < 320; i += 256) s_esc[i] = esc[e0 * 10 + i];   // FIXED: full 320 coverage
    __syncthreads();

    // ---- phase 1: h = silu(esc @ Wfc1 / sqrt(10)), tf32-rounded, transposed ----
    {
        int e = t & 31, q = t >> 5;     // 8 col-groups of 8
        float es[10];
#pragma unroll
        for (int u = 0; u < 10; ++u) es[u] = s_esc[e * 10 + u];
#pragma unroll
        for (int c = 0; c < 8; ++c) {
            int col = q * 8 + c;
            float acc = 0.f;
#pragma unroll
            for (int u = 0; u < 10; ++u) acc += es[u] * s_w1[u * 64 + col];
            s_hT[col * SH_STRIDE + e] = tf32r(siluf_(acc * INV_S10));
        }
    }
    __syncthreads();

    // ---- phase 2: w = h @ Wfc2 / 8 via tf32 m16n8k8 MMA ----
    // warp wp: m-tile (wp&1)*16, n-tiles T = (wp>>1)*6 .. +5, K=64 in one pass.
    {
        const int m0   = (wp & 1) * 16;
        const int tb   = (wp >> 1) * 6;
        const int row  = lane >> 2, kc = lane & 3;
        const float* w2f = (const float*)d_w2f[layer];

        float c[6][4];
#pragma unroll
        for (int i = 0; i < 6; ++i)
#pragma unroll
            for (int j = 0; j < 4; ++j) c[i][j] = 0.f;

#pragma unroll
        for (int S = 0; S < 8; ++S) {
            int kk = S * 8;
            uint32_t a0 = __float_as_uint(s_hT[(kk + kc)     * SH_STRIDE + m0 + row]);
            uint32_t a1 = __float_as_uint(s_hT[(kk + kc)     * SH_STRIDE + m0 + row + 8]);
            uint32_t a2 = __float_as_uint(s_hT[(kk + kc + 4) * SH_STRIDE + m0 + row]);
            uint32_t a3 = __float_as_uint(s_hT[(kk + kc + 4) * SH_STRIDE + m0 + row + 8]);
#pragma unroll
            for (int tt = 0; tt < 6; ++tt) {
                int T = tb + tt;
                const float* bp = w2f + ((S * 24 + T) * 2) * 32 + lane;
                uint32_t b0 = __float_as_uint(__ldg(bp));
                uint32_t b1 = __float_as_uint(__ldg(bp + 32));
                mma_tf32(c[tt], a0, a1, a2, a3, b0, b1);
            }
        }
        // all warps done reading s_hT -> safe to overwrite the union with s_w
        __syncthreads();
#pragma unroll
        for (int tt = 0; tt < 6; ++tt) {
            int col = (tb + tt) * 8 + kc * 2;
            int r0  = m0 + row;
            s_w[r0 * SW_STRIDE + col]           = c[tt][0] * INV_S64;
            s_w[r0 * SW_STRIDE + col + 1]       = c[tt][1] * INV_S64;
            s_w[(r0 + 8) * SW_STRIDE + col]     = c[tt][2] * INV_S64;
            s_w[(r0 + 8) * SW_STRIDE + col + 1] = c[tt][3] * INV_S64;
        }
    }
    __syncthreads();

    // ---- phase 3: warp-per-edge messages, vectorized red.v4 scatter ----
    {
#pragma unroll
        for (int ei = 0; ei < 4; ++ei) {
            int e  = wp * 4 + ei;
            int ge = e0 + e;
            int sn = __ldg(src + ge), dn = __ldg(dst + ge);
            float4 sh4 = __ldg((const float4*)(sh + ge * 4));
            float s0 = sh4.x, vx = sh4.y, vy = sh4.z, vz = sh4.w;
            const float* we  = s_w + e * SW_STRIDE;
            const float* hsp = d_hs + sn * 64;
            const float* hvp = d_hv + sn * 96;
            float* msd = d_Ms + dn * 96;
            float* mvd = d_Mv + dn * 288;

            if (lane < 16) {
                int j0 = lane * 4;
                float4 h4 = *(const float4*)(hsp + j0);
                float4 wa = *(const float4*)(we + j0);
                red4(msd + j0, make_float4(h4.x * s0 * wa.x, h4.y * s0 * wa.y,
                                           h4.z * s0 * wa.z, h4.w * s0 * wa.w));
            } else if (lane < 24) {
                int jp0 = (lane - 16) * 4;
                const float* gp = hvp + jp0 * 3;
                float4 ga = *(const float4*)gp;
                float4 gb = *(const float4*)(gp + 4);
                float4 gc = *(const float4*)(gp + 8);
                float4 w4 = *(const float4*)(we + 160 + jp0);
                float4 v;
                v.x = (ga.x * vx + ga.y * vy + ga.z * vz) * INV_S3 * w4.x;
                v.y = (ga.w * vx + gb.x * vy + gb.y * vz) * INV_S3 * w4.y;
                v.z = (gb.z * vx + gb.w * vy + gc.x * vz) * INV_S3 * w4.z;
                v.w = (gc.y * vx + gc.z * vy + gc.w * vz) * INV_S3 * w4.w;
                red4(msd + 64 + jp0, v);
            }
            {
                int f0 = lane * 4;
                float v[4];
#pragma unroll
                for (int c2 = 0; c2 < 4; ++c2) {
                    int f = f0 + c2, j = f / 3, i2 = f - 3 * j;
                    float shvi = (i2 == 0) ? vx : ((i2 == 1) ? vy : vz);
                    v[c2] = hsp[j] * shvi * we[64 + j];
                }
                red4(mvd + f0, make_float4(v[0], v[1], v[2], v[3]));
                if (lane < 16) {
                    int f1 = 128 + lane * 4;
                    float u2[4];
#pragma unroll
                    for (int c2 = 0; c2 < 4; ++c2) {
                        int f = f1 + c2, j = f / 3, i2 = f - 3 * j;
                        float shvi = (i2 == 0) ? vx : ((i2 == 1) ? vy : vz);
                        u2[c2] = hsp[j] * shvi * we[64 + j];
                    }
                    red4(mvd + f1, make_float4(u2[0], u2[1], u2[2], u2[3]));
                }
            }
            if (lane < 24) {
                int i0 = lane * 4;
                float4 g4 = *(const float4*)(hvp + i0);
                float4 v;
                v.x = g4.x * s0 * we[128 + (i0    ) / 3];
                v.y = g4.y * s0 * we[128 + (i0 + 1) / 3];
                v.z = g4.z * s0 * we[128 + (i0 + 2) / 3];
                v.w = g4.w * s0 * we[128 + (i0 + 3) / 3];
                red4(mvd + 192 + i0, v);
            }
        }
    }
}

// ---------------- kernel C: node finalize (warp per 2 nodes) ---------------
template <int OS, bool L1>
__global__ void __launch_bounds__(256) k_node_post(
    const float* __restrict__ attr,
    const float* __restrict__ W2s, const float* __restrict__ W2v,
    const float* __restrict__ Wa,  float* __restrict__ out)
{
    const int l  = threadIdx.x & 31;
    const int n0 = (blockIdx.x * 8 + (threadIdx.x >> 5)) * 2;
    if (n0 >= N_NODES) return;
    const bool actB = (n0 + 1 < N_NODES);
    const int nA = n0, nB = actB ? n0 + 1 : n0;

    float aA = attr[nA], aB = attr[nB];
    float idA = 1.0f / fmaxf(d_deg[nA], 1.0f);
    float idB = 1.0f / fmaxf(d_deg[nB], 1.0f);

    float msA[3], msB[3], mvA[3][3], mvB[3][3];
#pragma unroll
    for (int r = 0; r < 3; ++r) {
        msA[r] = d_Ms[nA * 96 + r * 32 + l] * idA;
        msB[r] = d_Ms[nB * 96 + r * 32 + l] * idB;
#pragma unroll
        for (int i = 0; i < 3; ++i) {
            mvA[r][i] = d_Mv[nA * 288 + (r * 32 + l) * 3 + i] * idA;
            mvB[r][i] = d_Mv[nB * 288 + (r * 32 + l) * 3 + i] * idB;
        }
    }

    float wa0 = Wa[l], wa1 = Wa[32 + l], wa2 = Wa[64 + l];
    float apA = msA[0] * wa0 + msA[1] * wa1 + msA[2] * wa2;
    float apB = msB[0] * wa0 + msB[1] * wa1 + msB[2] * wa2;
#pragma unroll
    for (int o = 16; o > 0; o >>= 1) {
        apA += __shfl_xor_sync(0xffffffffu, apA, o);
        apB += __shfl_xor_sync(0xffffffffu, apB, o);
    }
    float alA = apA * INV_S96 * aA;
    float alB = apB * INV_S96 * aB;

    float osA0 = 0.f, osA1 = 0.f, osA2 = 0.f, ovA0 = 0.f, ovA1 = 0.f, ovA2 = 0.f;
    float osB0 = 0.f, osB1 = 0.f, osB2 = 0.f, ovB0 = 0.f, ovB1 = 0.f, ovB2 = 0.f;
#pragma unroll
    for (int u = 0; u < 96; ++u) {
        int r = u >> 5, lu = u & 31;
        float w0 = W2s[u * OS + l];
        float w1 = W2s[u * OS + 32 + l];
        float w2 = (OS == 96) ? W2s[u * OS + 64 + l] : 0.f;
        float wv = W2v[u * 32 + l];
        float mA  = __shfl_sync(0xffffffffu, msA[r], lu);
        float mB  = __shfl_sync(0xffffffffu, msB[r], lu);
        float vA0 = __shfl_sync(0xffffffffu, mvA[r][0], lu);
        float vA1 = __shfl_sync(0xffffffffu, mvA[r][1], lu);
        float vA2 = __shfl_sync(0xffffffffu, mvA[r][2], lu);
        float vB0 = __shfl_sync(0xffffffffu, mvB[r][0], lu);
        float vB1 = __shfl_sync(0xffffffffu, mvB[r][1], lu);
        float vB2 = __shfl_sync(0xffffffffu, mvB[r][2], lu);
        osA0 += mA * w0; osA1 += mA * w1;
        osB0 += mB * w0; osB1 += mB * w1;
        if (OS == 96) { osA2 += mA * w2; osB2 += mB * w2; }
        ovA0 += vA0 * wv; ovA1 += vA1 * wv; ovA2 += vA2 * wv;
        ovB0 += vB0 * wv; ovB1 += vB1 * wv; ovB2 += vB2 * wv;
    }

    {
        float f = aA * INV_S96;
        float sA = d_scs[nA * OS + l]      + alA * (osA0 * f);
        float sB = d_scs[nA * OS + 32 + l] + alA * (osA1 * f);
        float sC = (OS == 96) ? (d_scs[nA * OS + 64 + l] + alA * (osA2 * f)) : 0.f;
        float v0 = d_scv[nA * 96 + l * 3 + 0] + alA * (ovA0 * f);
        float v1 = d_scv[nA * 96 + l * 3 + 1] + alA * (ovA1 * f);
        float v2 = d_scv[nA * 96 + l * 3 + 2] + alA * (ovA2 * f);
        if (L1) {
            d_gs[nA * 64 + l]      = siluf_(sA);
            d_gs[nA * 64 + 32 + l] = siluf_(sB);
            float sg = sigmoidf_(sC);
            d_v1[nA * 96 + l * 3 + 0] = v0 * sg;
            d_v1[nA * 96 + l * 3 + 1] = v1 * sg;
            d_v1[nA * 96 + l * 3 + 2] = v2 * sg;
        } else {
            out[nA * 160 + l]      = sA;
            out[nA * 160 + 32 + l] = sB;
            out[nA * 160 + 64 + l * 3 + 0] = v0;
            out[nA * 160 + 64 + l * 3 + 1] = v1;
            out[nA * 160 + 64 + l * 3 + 2] = v2;
        }
    }
    if (actB) {
        float f = aB * INV_S96;
        float sA = d_scs[nB * OS + l]      + alB * (osB0 * f);
        float sB2 = d_scs[nB * OS + 32 + l] + alB * (osB1 * f);
        float sC = (OS == 96) ? (d_scs[nB * OS + 64 + l] + alB * (osB2 * f)) : 0.f;
        float v0 = d_scv[nB * 96 + l * 3 + 0] + alB * (ovB0 * f);
        float v1 = d_scv[nB * 96 + l * 3 + 1] + alB * (ovB1 * f);
        float v2 = d_scv[nB * 96 + l * 3 + 2] + alB * (ovB2 * f);
        if (L1) {
            d_gs[nB * 64 + l]      = siluf_(sA);
            d_gs[nB * 64 + 32 + l] = siluf_(sB2);
            float sg = sigmoidf_(sC);
            d_v1[nB * 96 + l * 3 + 0] = v0 * sg;
            d_v1[nB * 96 + l * 3 + 1] = v1 * sg;
            d_v1[nB * 96 + l * 3 + 2] = v2 * sg;
        } else {
            out[nB * 160 + l]      = sA;
            out[nB * 160 + 32 + l] = sB2;
            out[nB * 160 + 64 + l * 3 + 0] = v0;
            out[nB * 160 + 64 + l * 3 + 1] = v1;
            out[nB * 160 + 64 + l * 3 + 2] = v2;
        }
    }
}

// ---------------- launch ----------------------------------------------------
extern "C" void kernel_launch(void* const* d_in, const int* in_sizes, int n_in,
                              void* d_out, int out_size)
{
    const float* node_s = (const float*)d_in[0];
    const float* node_v = (const float*)d_in[1];
    const float* attr   = (const float*)d_in[2];
    const int*   src    = (const int*)d_in[3];
    const int*   dst    = (const int*)d_in[4];
    const float* sh     = (const float*)d_in[5];
    const float* esc    = (const float*)d_in[6];
    const float* w1[9];
    const float* w2[9];
    for (int i = 0; i < 9; ++i) { w1[i] = (const float*)d_in[7 + i]; w2[i] = (const float*)d_in[16 + i]; }
    float* out = (float*)d_out;

    cudaFuncSetAttribute(k_edge, cudaFuncAttributeMaxDynamicSharedMemorySize, B_SMEM_BYTES);

    const int NPB = 16;  // nodes per block (8 warps x 2)
    const int nodeBlocks = (N_NODES + NPB - 1) / NPB;

    k_deg_zero<<<(N_NODES + 255) / 256, 256>>>();
    k_deg<<<(N_EDGES + 255) / 256, 256>>>(dst);
    k_prep<<<96, 256>>>(w1[5], w2[5]);

    // ---- layer 1 (o_s = 96) ----
    k_node_pre<96, false><<<nodeBlocks, 256>>>(node_s, node_v, attr,
                                               w1[0], w1[1], w1[2], w1[3]);
    k_edge<<<N_EDGES / EPB, 256, B_SMEM_BYTES>>>(esc, sh, src, dst, w1[4], 0);
    k_node_post<96, true><<<nodeBlocks, 256>>>(attr, w1[6], w1[7], w1[8], out);

    // ---- layer 2 (o_s = 64) ----
    k_node_pre<64, true><<<nodeBlocks, 256>>>(nullptr, nullptr, attr,
                                              w2[0], w2[1], w2[2], w2[3]);
    k_edge<<<N_EDGES / EPB, 256, B_SMEM_BYTES>>>(esc, sh, src, dst, w2[4], 1);
    k_node_post<64, false><<<nodeBlocks, 256>>>(attr, w2[6], w2[7], w2[8], out);

    (void)in_sizes; (void)n_in; (void)out_size;
}

// round 16
// speedup vs baseline: 1.3807x; 1.0102x over previous
#include <cuda_runtime.h>
#include <math.h>
#include <stdint.h>

#define N_NODES 50000
#define N_EDGES 400000
#define EPB 32   // edges per block in k_edge

// Scale constants
#define INV_S64  0.125f                  // 1/sqrt(64)
#define INV_S32  0.17677669529663687f    // 1/sqrt(32)
#define INV_S10  0.31622776601683794f    // 1/sqrt(10)
#define INV_S96  0.10206207261596575f    // 1/sqrt(96)
#define INV_S3   0.57735026918962576f    // 1/sqrt(3)

// ---------------- scratch (device globals; no allocation allowed) ----------
__device__ __align__(16) float d_hs [N_NODES * 64];
__device__ __align__(16) float d_hv [N_NODES * 96];
__device__ __align__(16) float d_scs[N_NODES * 96];
__device__ __align__(16) float d_scv[N_NODES * 96];
__device__ __align__(16) float d_Ms [N_NODES * 96];
__device__ __align__(16) float d_Mv [N_NODES * 288];
__device__ float d_deg[N_NODES];
__device__ __align__(16) float d_gs [N_NODES * 64];
__device__ __align__(16) float d_v1 [N_NODES * 96];
__device__ float d_w2f[2][12288];       // Wfc2 tf32, MMA-fragment-packed, per layer

__device__ __forceinline__ float sigmoidf_(float x) { return 1.0f / (1.0f + __expf(-x)); }
__device__ __forceinline__ float siluf_(float x)    { return x / (1.0f + __expf(-x)); }

__device__ __forceinline__ float tf32r(float x) {
    uint32_t u;
    asm("cvt.rna.tf32.f32 %0, %1;" : "=r"(u) : "f"(x));
    return __uint_as_float(u);
}

__device__ __forceinline__ void mma_tf32(float c[4],
    uint32_t a0, uint32_t a1, uint32_t a2, uint32_t a3,
    uint32_t b0, uint32_t b1)
{
    asm volatile(
        "mma.sync.aligned.m16n8k8.row.col.f32.tf32.tf32.f32 "
        "{%0,%1,%2,%3},{%4,%5,%6,%7},{%8,%9},{%0,%1,%2,%3};"
        : "+f"(c[0]), "+f"(c[1]), "+f"(c[2]), "+f"(c[3])
        : "r"(a0), "r"(a1), "r"(a2), "r"(a3), "r"(b0), "r"(b1));
}

__device__ __forceinline__ void red4(float* p, float4 v) {
    atomicAdd(reinterpret_cast<float4*>(p), v);
}

// ---------------- degree + weight prep -------------------------------------
__global__ void k_deg_zero() {
    int i = blockIdx.x * blockDim.x + threadIdx.x;
    if (i < N_NODES) d_deg[i] = 0.0f;
}
__global__ void k_deg(const int* __restrict__ dst) {
    int i = blockIdx.x * blockDim.x + threadIdx.x;
    if (i < N_EDGES) atomicAdd(&d_deg[dst[i]], 1.0f);
}

// Pack Wfc2 (64k x 192n) into MMA B-fragment order, tf32-rounded.
__global__ void k_prep(const float* __restrict__ W2a, const float* __restrict__ W2b) {
    int t = blockIdx.x * 256 + threadIdx.x;
    if (t >= 24576) return;
    int lay = t / 12288, r = t % 12288;
    int S = r / 1536;
    int rem = r % 1536;
    int T = rem / 64;
    int rem2 = rem % 64;
    int half = rem2 >> 5, lane = rem2 & 31;
    int row = lane >> 2, kc = lane & 3;
    const float* W = lay ? W2b : W2a;
    d_w2f[lay][r] = tf32r(W[(8 * S + kc + 4 * half) * 192 + 8 * T + row]);
}

// ---------------- kernel A: node pre-linears (warp per 4 nodes) ------------
#define PNODES 4
template <int OS, bool SCR>
__global__ void __launch_bounds__(256) k_node_pre(
    const float* __restrict__ ns_in, const float* __restrict__ nv_in,
    const float* __restrict__ attr,
    const float* __restrict__ Wscs, const float* __restrict__ Wscv,
    const float* __restrict__ W1s,  const float* __restrict__ W1v)
{
    const int l  = threadIdx.x & 31;
    const int n0 = (blockIdx.x * 8 + (threadIdx.x >> 5)) * PNODES;
    if (n0 >= N_NODES) return;

    const float* ns = SCR ? d_gs : ns_in;
    const float* nv = SCR ? d_v1 : nv_in;

    int nn[PNODES];
    bool act[PNODES];
#pragma unroll
    for (int p = 0; p < PNODES; ++p) {
        act[p] = (n0 + p < N_NODES);
        nn[p]  = act[p] ? n0 + p : n0;
    }

    float a[PNODES], ns0[PNODES], ns1[PNODES];
    float nv0[PNODES], nv1[PNODES], nv2[PNODES];
#pragma unroll
    for (int p = 0; p < PNODES; ++p) {
        a[p]   = attr[nn[p]];
        ns0[p] = ns[nn[p] * 64 + l];
        ns1[p] = ns[nn[p] * 64 + 32 + l];
        nv0[p] = nv[nn[p] * 96 + l * 3 + 0];
        nv1[p] = nv[nn[p] * 96 + l * 3 + 1];
        nv2[p] = nv[nn[p] * 96 + l * 3 + 2];
    }

    float hs0[PNODES] = {}, hs1[PNODES] = {};
    float sc0[PNODES] = {}, sc1[PNODES] = {}, sc2[PNODES] = {};
#pragma unroll
    for (int u = 0; u < 64; ++u) {
        float w1a = W1s[u * 64 + l];
        float w1b = W1s[u * 64 + 32 + l];
        float wsa = Wscs[u * OS + l];
        float wsb = Wscs[u * OS + 32 + l];
        float wsc = (OS == 96) ? Wscs[u * OS + 64 + l] : 0.f;
#pragma unroll
        for (int p = 0; p < PNODES; ++p) {
            float nu = __shfl_sync(0xffffffffu, (u < 32) ? ns0[p] : ns1[p], u & 31);
            hs0[p] += nu * w1a; hs1[p] += nu * w1b;
            sc0[p] += nu * wsa; sc1[p] += nu * wsb;
            if (OS == 96) sc2[p] += nu * wsc;
        }
    }

    float hv0[PNODES] = {}, hv1[PNODES] = {}, hv2[PNODES] = {};
    float sv0[PNODES] = {}, sv1[PNODES] = {}, sv2[PNODES] = {};
#pragma unroll
    for (int u = 0; u < 32; ++u) {
        float wl = W1v [u * 32 + l];
        float ws = Wscv[u * 32 + l];
#pragma unroll
        for (int p = 0; p < PNODES; ++p) {
            float b0 = __shfl_sync(0xffffffffu, nv0[p], u);
            float b1 = __shfl_sync(0xffffffffu, nv1[p], u);
            float b2 = __shfl_sync(0xffffffffu, nv2[p], u);
            hv0[p] += b0 * wl; hv1[p] += b1 * wl; hv2[p] += b2 * wl;
            sv0[p] += b0 * ws; sv1[p] += b1 * ws; sv2[p] += b2 * ws;
        }
    }

#pragma unroll
    for (int p = 0; p < PNODES; ++p) {
        if (!act[p]) continue;
        int n = nn[p];
        float fs = a[p] * INV_S64, fv = a[p] * INV_S32;
        d_hs[n * 64 + l]       = hs0[p] * fs;
        d_hs[n * 64 + 32 + l]  = hs1[p] * fs;
        d_scs[n * OS + l]      = sc0[p] * fs;
        d_scs[n * OS + 32 + l] = sc1[p] * fs;
        if (OS == 96) d_scs[n * OS + 64 + l] = sc2[p] * fs;
        d_hv [n * 96 + l * 3 + 0] = hv0[p] * fv;
        d_hv [n * 96 + l * 3 + 1] = hv1[p] * fv;
        d_hv [n * 96 + l * 3 + 2] = hv2[p] * fv;
        d_scv[n * 96 + l * 3 + 0] = sv0[p] * fv;
        d_scv[n * 96 + l * 3 + 1] = sv1[p] * fv;
        d_scv[n * 96 + l * 3 + 2] = sv2[p] * fv;
        d_Ms[n * 96 + l] = 0.f; d_Ms[n * 96 + 32 + l] = 0.f; d_Ms[n * 96 + 64 + l] = 0.f;
#pragma unroll
        for (int r = 0; r < 9; ++r) d_Mv[n * 288 + r * 32 + l] = 0.f;
    }
}

// ---------------- kernel B: fused edge MLP (tf32 MMA) + messages + scatter -
// 32 edges / block, 256 threads (8 warps), 4 CTAs/SM.  [UNCHANGED from R13]
#define SH_STRIDE 40
#define SW_STRIDE 196
#define B_SMEM_FLOATS (EPB * SW_STRIDE)       // 6272
#define B_SMEM_BYTES  (B_SMEM_FLOATS * 4)     // 25088

__global__ void __launch_bounds__(256, 4) k_edge(
    const float* __restrict__ esc, const float* __restrict__ sh,
    const int* __restrict__ src,   const int* __restrict__ dst,
    const float* __restrict__ Wfc1, int layer)
{
    extern __shared__ float sm[];
    float* s_w1  = sm;                  // 640  (dead after phase 1)
    float* s_esc = sm + 640;            // 320  (dead after phase 1)
    float* s_hT  = sm + 960;            // 2560 (dead after phase-2 MMA loop)
    float* s_w   = sm;                  // 6272 (aliases all of the above)

    const int t  = threadIdx.x;
    const int e0 = blockIdx.x * EPB;
    const int lane = t & 31, wp = t >> 5;

    for (int i = t; i < 640; i += 256) s_w1[i]  = Wfc1[i];
    for (int i = t; i < 320; i += 256) s_esc[i] = esc[e0 * 10 + i];
    __syncthreads();

    // ---- phase 1: h = silu(esc @ Wfc1 / sqrt(10)), tf32-rounded, transposed ----
    {
        int e = t & 31, q = t >> 5;     // 8 col-groups of 8
        float es[10];
#pragma unroll
        for (int u = 0; u < 10; ++u) es[u] = s_esc[e * 10 + u];
#pragma unroll
        for (int c = 0; c < 8; ++c) {
            int col = q * 8 + c;
            float acc = 0.f;
#pragma unroll
            for (int u = 0; u < 10; ++u) acc += es[u] * s_w1[u * 64 + col];
            s_hT[col * SH_STRIDE + e] = tf32r(siluf_(acc * INV_S10));
        }
    }
    __syncthreads();

    // ---- phase 2: w = h @ Wfc2 / 8 via tf32 m16n8k8 MMA ----
    {
        const int m0   = (wp & 1) * 16;
        const int tb   = (wp >> 1) * 6;
        const int row  = lane >> 2, kc = lane & 3;
        const float* w2f = (const float*)d_w2f[layer];

        float c[6][4];
#pragma unroll
        for (int i = 0; i < 6; ++i)
#pragma unroll
            for (int j = 0; j < 4; ++j) c[i][j] = 0.f;

#pragma unroll
        for (int S = 0; S < 8; ++S) {
            int kk = S * 8;
            uint32_t a0 = __float_as_uint(s_hT[(kk + kc)     * SH_STRIDE + m0 + row]);
            uint32_t a1 = __float_as_uint(s_hT[(kk + kc)     * SH_STRIDE + m0 + row + 8]);
            uint32_t a2 = __float_as_uint(s_hT[(kk + kc + 4) * SH_STRIDE + m0 + row]);
            uint32_t a3 = __float_as_uint(s_hT[(kk + kc + 4) * SH_STRIDE + m0 + row + 8]);
#pragma unroll
            for (int tt = 0; tt < 6; ++tt) {
                int T = tb + tt;
                const float* bp = w2f + ((S * 24 + T) * 2) * 32 + lane;
                uint32_t b0 = __float_as_uint(__ldg(bp));
                uint32_t b1 = __float_as_uint(__ldg(bp + 32));
                mma_tf32(c[tt], a0, a1, a2, a3, b0, b1);
            }
        }
        __syncthreads();
#pragma unroll
        for (int tt = 0; tt < 6; ++tt) {
            int col = (tb + tt) * 8 + kc * 2;
            int r0  = m0 + row;
            s_w[r0 * SW_STRIDE + col]           = c[tt][0] * INV_S64;
            s_w[r0 * SW_STRIDE + col + 1]       = c[tt][1] * INV_S64;
            s_w[(r0 + 8) * SW_STRIDE + col]     = c[tt][2] * INV_S64;
            s_w[(r0 + 8) * SW_STRIDE + col + 1] = c[tt][3] * INV_S64;
        }
    }
    __syncthreads();

    // ---- phase 3: warp-per-edge messages, vectorized red.v4 scatter ----
    {
#pragma unroll
        for (int ei = 0; ei < 4; ++ei) {
            int e  = wp * 4 + ei;
            int ge = e0 + e;
            int sn = __ldg(src + ge), dn = __ldg(dst + ge);
            float4 sh4 = __ldg((const float4*)(sh + ge * 4));
            float s0 = sh4.x, vx = sh4.y, vy = sh4.z, vz = sh4.w;
            const float* we  = s_w + e * SW_STRIDE;
            const float* hsp = d_hs + sn * 64;
            const float* hvp = d_hv + sn * 96;
            float* msd = d_Ms + dn * 96;
            float* mvd = d_Mv + dn * 288;

            if (lane < 16) {
                int j0 = lane * 4;
                float4 h4 = *(const float4*)(hsp + j0);
                float4 wa = *(const float4*)(we + j0);
                red4(msd + j0, make_float4(h4.x * s0 * wa.x, h4.y * s0 * wa.y,
                                           h4.z * s0 * wa.z, h4.w * s0 * wa.w));
            } else if (lane < 24) {
                int jp0 = (lane - 16) * 4;
                const float* gp = hvp + jp0 * 3;
                float4 ga = *(const float4*)gp;
                float4 gb = *(const float4*)(gp + 4);
                float4 gc = *(const float4*)(gp + 8);
                float4 w4 = *(const float4*)(we + 160 + jp0);
                float4 v;
                v.x = (ga.x * vx + ga.y * vy + ga.z * vz) * INV_S3 * w4.x;
                v.y = (ga.w * vx + gb.x * vy + gb.y * vz) * INV_S3 * w4.y;
                v.z = (gb.z * vx + gb.w * vy + gc.x * vz) * INV_S3 * w4.z;
                v.w = (gc.y * vx + gc.z * vy + gc.w * vz) * INV_S3 * w4.w;
                red4(msd + 64 + jp0, v);
            }
            {
                int f0 = lane * 4;
                float v[4];
#pragma unroll
                for (int c2 = 0; c2 < 4; ++c2) {
                    int f = f0 + c2, j = f / 3, i2 = f - 3 * j;
                    float shvi = (i2 == 0) ? vx : ((i2 == 1) ? vy : vz);
                    v[c2] = hsp[j] * shvi * we[64 + j];
                }
                red4(mvd + f0, make_float4(v[0], v[1], v[2], v[3]));
                if (lane < 16) {
                    int f1 = 128 + lane * 4;
                    float u2[4];
#pragma unroll
                    for (int c2 = 0; c2 < 4; ++c2) {
                        int f = f1 + c2, j = f / 3, i2 = f - 3 * j;
                        float shvi = (i2 == 0) ? vx : ((i2 == 1) ? vy : vz);
                        u2[c2] = hsp[j] * shvi * we[64 + j];
                    }
                    red4(mvd + f1, make_float4(u2[0], u2[1], u2[2], u2[3]));
                }
            }
            if (lane < 24) {
                int i0 = lane * 4;
                float4 g4 = *(const float4*)(hvp + i0);
                float4 v;
                v.x = g4.x * s0 * we[128 + (i0    ) / 3];
                v.y = g4.y * s0 * we[128 + (i0 + 1) / 3];
                v.z = g4.z * s0 * we[128 + (i0 + 2) / 3];
                v.w = g4.w * s0 * we[128 + (i0 + 3) / 3];
                red4(mvd + 192 + i0, v);
            }
        }
    }
}

// ---------------- kernel C: node finalize (warp per 4 nodes) ---------------
template <int OS, bool L1F>
__global__ void __launch_bounds__(256) k_node_post(
    const float* __restrict__ attr,
    const float* __restrict__ W2s, const float* __restrict__ W2v,
    const float* __restrict__ Wa,  float* __restrict__ out)
{
    const int l  = threadIdx.x & 31;
    const int n0 = (blockIdx.x * 8 + (threadIdx.x >> 5)) * PNODES;
    if (n0 >= N_NODES) return;

    int nn[PNODES];
    bool act[PNODES];
#pragma unroll
    for (int p = 0; p < PNODES; ++p) {
        act[p] = (n0 + p < N_NODES);
        nn[p]  = act[p] ? n0 + p : n0;
    }

    float a[PNODES], inv[PNODES];
#pragma unroll
    for (int p = 0; p < PNODES; ++p) {
        a[p]   = attr[nn[p]];
        inv[p] = 1.0f / fmaxf(d_deg[nn[p]], 1.0f);
    }

    float ms[3][PNODES], mv[3][3][PNODES];
#pragma unroll
    for (int r = 0; r < 3; ++r)
#pragma unroll
        for (int p = 0; p < PNODES; ++p) {
            ms[r][p] = d_Ms[nn[p] * 96 + r * 32 + l] * inv[p];
#pragma unroll
            for (int i = 0; i < 3; ++i)
                mv[r][i][p] = d_Mv[nn[p] * 288 + (r * 32 + l) * 3 + i] * inv[p];
        }

    float wa0 = Wa[l], wa1 = Wa[32 + l], wa2 = Wa[64 + l];
    float al[PNODES];
#pragma unroll
    for (int p = 0; p < PNODES; ++p) {
        float ap = ms[0][p] * wa0 + ms[1][p] * wa1 + ms[2][p] * wa2;
#pragma unroll
        for (int o = 16; o > 0; o >>= 1) ap += __shfl_xor_sync(0xffffffffu, ap, o);
        al[p] = ap * INV_S96 * a[p];
    }

    float os0[PNODES] = {}, os1[PNODES] = {}, os2[PNODES] = {};
    float ov0[PNODES] = {}, ov1[PNODES] = {}, ov2[PNODES] = {};
#pragma unroll
    for (int u = 0; u < 96; ++u) {
        int r = u >> 5, lu = u & 31;
        float w0 = W2s[u * OS + l];
        float w1 = W2s[u * OS + 32 + l];
        float w2 = (OS == 96) ? W2s[u * OS + 64 + l] : 0.f;
        float wv = W2v[u * 32 + l];
#pragma unroll
        for (int p = 0; p < PNODES; ++p) {
            float m  = __shfl_sync(0xffffffffu, ms[r][p], lu);
            float v0 = __shfl_sync(0xffffffffu, mv[r][0][p], lu);
            float v1 = __shfl_sync(0xffffffffu, mv[r][1][p], lu);
            float v2 = __shfl_sync(0xffffffffu, mv[r][2][p], lu);
            os0[p] += m * w0; os1[p] += m * w1;
            if (OS == 96) os2[p] += m * w2;
            ov0[p] += v0 * wv; ov1[p] += v1 * wv; ov2[p] += v2 * wv;
        }
    }

#pragma unroll
    for (int p = 0; p < PNODES; ++p) {
        if (!act[p]) continue;
        int n = nn[p];
        float f = a[p] * INV_S96;
        float sA = d_scs[n * OS + l]      + al[p] * (os0[p] * f);
        float sB = d_scs[n * OS + 32 + l] + al[p] * (os1[p] * f);
        float sC = (OS == 96) ? (d_scs[n * OS + 64 + l] + al[p] * (os2[p] * f)) : 0.f;
        float v0 = d_scv[n * 96 + l * 3 + 0] + al[p] * (ov0[p] * f);
        float v1 = d_scv[n * 96 + l * 3 + 1] + al[p] * (ov1[p] * f);
        float v2 = d_scv[n * 96 + l * 3 + 2] + al[p] * (ov2[p] * f);
        if (L1F) {
            d_gs[n * 64 + l]      = siluf_(sA);
            d_gs[n * 64 + 32 + l] = siluf_(sB);
            float sg = sigmoidf_(sC);
            d_v1[n * 96 + l * 3 + 0] = v0 * sg;
            d_v1[n * 96 + l * 3 + 1] = v1 * sg;
            d_v1[n * 96 + l * 3 + 2] = v2 * sg;
        } else {
            out[n * 160 + l]      = sA;
            out[n * 160 + 32 + l] = sB;
            out[n * 160 + 64 + l * 3 + 0] = v0;
            out[n * 160 + 64 + l * 3 + 1] = v1;
            out[n * 160 + 64 + l * 3 + 2] = v2;
        }
    }
}

// ---------------- launch ----------------------------------------------------
extern "C" void kernel_launch(void* const* d_in, const int* in_sizes, int n_in,
                              void* d_out, int out_size)
{
    const float* node_s = (const float*)d_in[0];
    const float* node_v = (const float*)d_in[1];
    const float* attr   = (const float*)d_in[2];
    const int*   src    = (const int*)d_in[3];
    const int*   dst    = (const int*)d_in[4];
    const float* sh     = (const float*)d_in[5];
    const float* esc    = (const float*)d_in[6];
    const float* w1[9];
    const float* w2[9];
    for (int i = 0; i < 9; ++i) { w1[i] = (const float*)d_in[7 + i]; w2[i] = (const float*)d_in[16 + i]; }
    float* out = (float*)d_out;

    cudaFuncSetAttribute(k_edge, cudaFuncAttributeMaxDynamicSharedMemorySize, B_SMEM_BYTES);

    const int NPB = 8 * PNODES;  // nodes per block (8 warps x 4)
    const int nodeBlocks = (N_NODES + NPB - 1) / NPB;

    k_deg_zero<<<(N_NODES + 255) / 256, 256>>>();
    k_deg<<<(N_EDGES + 255) / 256, 256>>>(dst);
    k_prep<<<96, 256>>>(w1[5], w2[5]);

    // ---- layer 1 (o_s = 96) ----
    k_node_pre<96, false><<<nodeBlocks, 256>>>(node_s, node_v, attr,
                                               w1[0], w1[1], w1[2], w1[3]);
    k_edge<<<N_EDGES / EPB, 256, B_SMEM_BYTES>>>(esc, sh, src, dst, w1[4], 0);
    k_node_post<96, true><<<nodeBlocks, 256>>>(attr, w1[6], w1[7], w1[8], out);

    // ---- layer 2 (o_s = 64) ----
    k_node_pre<64, true><<<nodeBlocks, 256>>>(nullptr, nullptr, attr,
                                              w2[0], w2[1], w2[2], w2[3]);
    k_edge<<<N_EDGES / EPB, 256, B_SMEM_BYTES>>>(esc, sh, src, dst, w2[4], 1);
    k_node_post<64, false><<<nodeBlocks, 256>>>(attr, w2[6], w2[7], w2[8], out);

    (void)in_sizes; (void)n_in; (void)out_size;
}